// round 5
// baseline (speedup 1.0000x reference)
#include <cuda_runtime.h>
#include <cuda_bf16.h>
#include <cstdint>

// ---------------- Problem constants ----------------
#define N_ROWS   131072      // 32*16*16*16
#define DIMK     256         // E_DIM
#define NCODE    512         // N_EMBED

// Output layout (concatenated flattened outputs, float32):
#define ZQ_OFF   0
#define VQ_OFF   33554432
#define CM_OFF   33554433
#define IDX_OFF  33554434
#define HIST_OFF 33685506

#define EPI_BLOCKS (N_ROWS / 8)   // 16384
#define MARGIN 8.0f               // ~7 sigma of int8-quant sim-error difference
#define CAND   16                 // candidate slots per row

// int8 quantization scale: q = round(x * 16); |x|max ~5.7 -> |q| <= ~92
#define QS     16.0f
#define INVQS2 0.0078125f         // 2 / (QS*QS) = 2/256

// ---------------- Device scratch (no allocations allowed) ----------------
__device__ __align__(16) int8_t g_ei[NCODE * DIMK];   // int8 embedding
__device__ float g_ce[NCODE];             // ||e_n||^2 (fp32, exact)
__device__ int   g_cnt[N_ROWS];           // candidate counts
__device__ int   g_cand[N_ROWS * CAND];   // candidate lists
__device__ float g_part[EPI_BLOCKS];      // loss partials

// ---------------- PTX helpers (portable to compute_103) ----------------
__device__ __forceinline__ uint32_t smem_u32(const void* p) {
    uint32_t a;
    asm("{ .reg .u64 t; cvta.to.shared.u64 t, %1; cvt.u32.u64 %0, t; }" : "=r"(a) : "l"(p));
    return a;
}
#define CP_ASYNC16(dst, src) \
    asm volatile("cp.async.cg.shared.global [%0], [%1], 16;" :: "r"(dst), "l"(src) : "memory")
#define CP_COMMIT() asm volatile("cp.async.commit_group;" ::: "memory")
#define CP_WAIT0()  asm volatile("cp.async.wait_group 0;" ::: "memory")
#define LDSM4(r0, r1, r2, r3, addr) \
    asm volatile("ldmatrix.sync.aligned.m8n8.x4.shared.b16 {%0,%1,%2,%3}, [%4];" \
        : "=r"(r0), "=r"(r1), "=r"(r2), "=r"(r3) : "r"(addr))
#define IMMA(d, a, b0, b1) \
    asm volatile("mma.sync.aligned.m16n8k32.row.col.s32.s8.s8.s32 " \
        "{%0,%1,%2,%3},{%4,%5,%6,%7},{%8,%9},{%0,%1,%2,%3};" \
        : "+r"((d)[0]), "+r"((d)[1]), "+r"((d)[2]), "+r"((d)[3]) \
        : "r"((a)[0]), "r"((a)[1]), "r"((a)[2]), "r"((a)[3]), "r"(b0), "r"(b1))

// Monotone float<->uint map for atomicMax on floats
__device__ __forceinline__ unsigned fmono(float x) {
    unsigned u = __float_as_uint(x);
    return (u & 0x80000000u) ? ~u : (u | 0x80000000u);
}
__device__ __forceinline__ float funmono(unsigned u) {
    return (u & 0x80000000u) ? __uint_as_float(u ^ 0x80000000u) : __uint_as_float(~u);
}

__device__ __forceinline__ unsigned quant4(float4 v) {
    int a = __float2int_rn(fminf(fmaxf(v.x * QS, -127.f), 127.f));
    int b = __float2int_rn(fminf(fmaxf(v.y * QS, -127.f), 127.f));
    int c = __float2int_rn(fminf(fmaxf(v.z * QS, -127.f), 127.f));
    int d = __float2int_rn(fminf(fmaxf(v.w * QS, -127.f), 127.f));
    return (unsigned)(a & 255) | ((unsigned)(b & 255) << 8) |
           ((unsigned)(c & 255) << 16) | ((unsigned)(d & 255) << 24);
}

// ---------------- SMEM layout for k_mma ----------------
// int8 rows padded to 272B: 272/4 = 68 banks == 4 mod 32 -> conflict-free ldmatrix
#define RS 272
#define SM_CE  0                      // 512 f32 = 2048B
#define SM_RB  2048                   // 128 u32 = 512B
#define SM_A   2560                   // 128 * 272 = 34816
#define SM_B   37376                  // 512 * 272 = 139264
#define SMEM_BYTES 176640

// ---------------- Kernel: prep (quantize emb, norms, zero counters/hist) ----------------
__global__ void k_prep(const float* __restrict__ emb, float* __restrict__ out) {
    int n = blockIdx.x;               // 512 blocks, 64 threads
    int t = threadIdx.x;
    float4 v = *(const float4*)(emb + (size_t)n * DIMK + t * 4);
    ((unsigned*)g_ei)[n * 64 + t] = quant4(v);
    // exact fp32 norm
    float s = v.x * v.x + v.y * v.y + v.z * v.z + v.w * v.w;
    #pragma unroll
    for (int o = 16; o > 0; o >>= 1) s += __shfl_down_sync(0xffffffffu, s, o);
    __shared__ float ws[2];
    if ((t & 31) == 0) ws[t >> 5] = s;
    __syncthreads();
    if (t == 0) g_ce[n] = ws[0] + ws[1];
    // zero candidate counters (512*64 = 32768 threads, 4 each)
    int g = n * 64 + t;
    #pragma unroll
    for (int k = 0; k < 4; k++) g_cnt[g + k * 32768] = 0;
    // zero histogram
    if (n == 0) {
        #pragma unroll
        for (int k = 0; k < 8; k++) out[HIST_OFF + t + k * 64] = 0.0f;
    }
}

// ---------------- Kernel: int8 IMMA GEMM + margin candidate collection ----------------
__global__ __launch_bounds__(512, 1)
void k_mma(const float* __restrict__ z) {
    extern __shared__ __align__(128) unsigned char smem[];
    float*    ceS     = (float*)(smem + SM_CE);
    unsigned* rowBest = (unsigned*)(smem + SM_RB);
    uint32_t sbase = smem_u32(smem);
    uint32_t sA = sbase + SM_A;
    uint32_t sB = sbase + SM_B;

    int tid = threadIdx.x, lane = tid & 31, wid = tid >> 5;
    int wm = wid & 3;        // M block: 32 rows
    int wn = wid >> 2;       // N block within chunk: 32 cols
    int rowBase = blockIdx.x * 128;

    for (int i = tid; i < NCODE; i += 512) ceS[i] = g_ce[i];
    if (tid < 128) rowBest[tid] = 0u;

    // ---- B: all 512 codes (int8) via cp.async ----
    {
        const char* src = (const char*)g_ei;
        #pragma unroll
        for (int it = 0; it < 16; it++) {
            int t = tid + it * 512;
            int r = t >> 4, c = t & 15;
            CP_ASYNC16(sB + r * RS + c * 16, src + r * 256 + c * 16);
        }
        CP_COMMIT();
    }
    // ---- A: load fp32 z, quantize to int8 in smem ----
    #pragma unroll
    for (int it = 0; it < 4; it++) {
        int t = tid + it * 512;
        int r = t >> 4, c = t & 15;   // 16 int8 per unit
        const float4* zp = (const float4*)(z + (size_t)(rowBase + r) * DIMK + c * 16);
        uint4 w;
        w.x = quant4(zp[0]);
        w.y = quant4(zp[1]);
        w.z = quant4(zp[2]);
        w.w = quant4(zp[3]);
        *(uint4*)(smem + SM_A + r * RS + c * 16) = w;
    }
    CP_WAIT0();
    __syncthreads();

    // ldmatrix base addresses (x4 tile: rows via lane&15, k-half via lane>>4)
    uint32_t aA = sA + (wm * 32 + (lane & 15)) * RS + ((lane >> 4) << 4);
    uint32_t bBbase = sB + (wn * 32 + (lane & 15)) * RS + ((lane >> 4) << 4);

    for (int ch = 0; ch < 4; ch++) {
        int acc[2][4][4];
        #pragma unroll
        for (int i = 0; i < 2; i++)
            #pragma unroll
            for (int j = 0; j < 4; j++)
                #pragma unroll
                for (int q = 0; q < 4; q++) acc[i][j][q] = 0;

        uint32_t bB = bBbase + (uint32_t)ch * 128 * RS;
        #pragma unroll
        for (int ks = 0; ks < 8; ks++) {
            uint32_t ko = ks * 32;
            uint32_t a0[4], a1[4];
            LDSM4(a0[0], a0[1], a0[2], a0[3], aA + ko);
            LDSM4(a1[0], a1[1], a1[2], a1[3], aA + 16 * RS + ko);
            uint32_t r0, r1, r2, r3, s0, s1, s2, s3;
            LDSM4(r0, r1, r2, r3, bB + ko);             // codes +0..15
            LDSM4(s0, s1, s2, s3, bB + 16 * RS + ko);   // codes +16..31
            IMMA(acc[0][0], a0, r0, r2);
            IMMA(acc[0][1], a0, r1, r3);
            IMMA(acc[0][2], a0, s0, s2);
            IMMA(acc[0][3], a0, s1, s3);
            IMMA(acc[1][0], a1, r0, r2);
            IMMA(acc[1][1], a1, r1, r3);
            IMMA(acc[1][2], a1, s0, s2);
            IMMA(acc[1][3], a1, s1, s3);
        }

        int cbase = ch * 128 + wn * 32 + 2 * (lane & 3);

        // ---- pass 1: per-row running max (monotone smem atomicMax) ----
        #pragma unroll
        for (int mh = 0; mh < 2; mh++) {
            #pragma unroll
            for (int rr = 0; rr < 2; rr++) {
                float m = -3.0e38f;
                #pragma unroll
                for (int nb = 0; nb < 4; nb++) {
                    float v0 = fmaf((float)acc[mh][nb][rr * 2],     -INVQS2, ceS[cbase + nb * 8]);
                    float v1 = fmaf((float)acc[mh][nb][rr * 2 + 1], -INVQS2, ceS[cbase + nb * 8 + 1]);
                    m = fmaxf(m, fmaxf(v0, v1));
                }
                m = fmaxf(m, __shfl_xor_sync(0xffffffffu, m, 1));
                m = fmaxf(m, __shfl_xor_sync(0xffffffffu, m, 2));
                if ((lane & 3) == 0)
                    atomicMax(&rowBest[wm * 32 + mh * 16 + rr * 8 + (lane >> 2)], fmono(m));
            }
        }
        __syncthreads();

        // ---- pass 2: collect candidates v >= rowBest - MARGIN (superset-safe) ----
        #pragma unroll
        for (int mh = 0; mh < 2; mh++) {
            #pragma unroll
            for (int rr = 0; rr < 2; rr++) {
                int lrow = wm * 32 + mh * 16 + rr * 8 + (lane >> 2);
                float thr = funmono(rowBest[lrow]) - MARGIN;
                int grow = rowBase + lrow;
                #pragma unroll
                for (int nb = 0; nb < 4; nb++) {
                    #pragma unroll
                    for (int q = 0; q < 2; q++) {
                        int col = cbase + nb * 8 + q;
                        float v = fmaf((float)acc[mh][nb][rr * 2 + q], -INVQS2, ceS[col]);
                        if (v >= thr) {
                            int pos = atomicAdd(&g_cnt[grow], 1);
                            if (pos < CAND) g_cand[grow * CAND + pos] = col;
                        }
                    }
                }
            }
        }
        // no sync needed: rowBest only grows; tighter thresholds stay superset-safe
    }
}

// ---------------- Kernel: fused resolve + gather epilogue ----------------
__global__ __launch_bounds__(256)
void k_epi(const float* __restrict__ z, const float* __restrict__ emb,
           float* __restrict__ out) {
    int w = threadIdx.x >> 5;
    int l = threadIdx.x & 31;
    int row = blockIdx.x * 8 + w;

    const float4* zp = (const float4*)(z + (size_t)row * DIMK);
    float4 a = zp[l * 2], b = zp[l * 2 + 1];

    // ---- resolve index ----
    int cnt = g_cnt[row];
    int idx;
    if (cnt <= 1) {
        idx = (cnt == 1) ? g_cand[row * CAND] : 0;
    } else {
        float best = -3.0e38f;
        idx = NCODE;
        bool full = (cnt > CAND);
        int n = full ? NCODE : cnt;
        for (int ci = 0; ci < n; ci++) {
            int c = full ? ci : g_cand[row * CAND + ci];
            const float4* ep = (const float4*)(emb + (size_t)c * DIMK);
            float4 e0 = ep[l * 2], e1 = ep[l * 2 + 1];
            float s = a.x * e0.x + a.y * e0.y + a.z * e0.z + a.w * e0.w
                    + b.x * e1.x + b.y * e1.y + b.z * e1.z + b.w * e1.w;
            #pragma unroll
            for (int o = 16; o > 0; o >>= 1) s += __shfl_xor_sync(0xffffffffu, s, o);
            float sim = g_ce[c] - 2.0f * s;
            if (sim > best || (sim == best && c < idx)) { best = sim; idx = c; }
        }
    }

    // ---- gather + loss ----
    const float* er = emb + (size_t)idx * DIMK;
    float* oq = out + ZQ_OFF + (size_t)row * DIMK;
    float4 e0 = *(const float4*)(er + l * 8);
    float4 e1 = *(const float4*)(er + l * 8 + 4);
    *(float4*)(oq + l * 8)     = e0;
    *(float4*)(oq + l * 8 + 4) = e1;
    float d0 = e0.x - a.x, d1 = e0.y - a.y, d2 = e0.z - a.z, d3 = e0.w - a.w;
    float d4 = e1.x - b.x, d5 = e1.y - b.y, d6 = e1.z - b.z, d7 = e1.w - b.w;
    float s = d0 * d0 + d1 * d1 + d2 * d2 + d3 * d3
            + d4 * d4 + d5 * d5 + d6 * d6 + d7 * d7;
    #pragma unroll
    for (int o = 16; o > 0; o >>= 1) s += __shfl_down_sync(0xffffffffu, s, o);

    __shared__ float ws[8];
    if (l == 0) {
        ws[w] = s;
        out[IDX_OFF + row] = (float)idx;
        atomicAdd(&out[HIST_OFF + idx], 1.0f);  // exact: integer-valued float adds
    }
    __syncthreads();
    if (threadIdx.x == 0) {
        float t = 0.0f;
        #pragma unroll
        for (int i = 0; i < 8; i++) t += ws[i];
        g_part[blockIdx.x] = t;
    }
}

// ---------------- Kernel: finalize losses ----------------
__global__ void k_final(float* __restrict__ out) {
    __shared__ float ps[256];
    int t = threadIdx.x;
    float s = 0.0f;
    for (int i = t; i < EPI_BLOCKS; i += 256) s += g_part[i];
    ps[t] = s;
    __syncthreads();
    if (t == 0) {
        float tot = 0.0f;
        for (int i = 0; i < 256; i++) tot += ps[i];
        float vq = tot / 33554432.0f;   // N_ROWS * DIMK
        out[VQ_OFF] = vq;
        out[CM_OFF] = 0.25f * vq;
    }
}

// ---------------- Launch ----------------
extern "C" void kernel_launch(void* const* d_in, const int* in_sizes, int n_in,
                              void* d_out, int out_size) {
    const float* z   = (const float*)d_in[0];
    const float* emb = (const float*)d_in[1];
    float* out = (float*)d_out;

    cudaFuncSetAttribute(k_mma, cudaFuncAttributeMaxDynamicSharedMemorySize, SMEM_BYTES);

    k_prep<<<NCODE, 64>>>(emb, out);
    k_mma<<<N_ROWS / 128, 512, SMEM_BYTES>>>(z);
    k_epi<<<EPI_BLOCKS, 256>>>(z, emb, out);
    k_final<<<1, 256>>>(out);
}

// round 7
// speedup vs baseline: 1.0077x; 1.0077x over previous
#include <cuda_runtime.h>
#include <cuda_bf16.h>
#include <cstdint>

// ---------------- Problem constants ----------------
#define N_ROWS   131072      // 32*16*16*16
#define DIMK     256         // E_DIM
#define NCODE    512         // N_EMBED

// Output layout (concatenated flattened outputs, float32):
#define ZQ_OFF   0
#define VQ_OFF   33554432
#define CM_OFF   33554433
#define IDX_OFF  33554434
#define HIST_OFF 33685506

#define EPI_BLOCKS (N_ROWS / 8)   // 16384
#define MARGIN 8.0f               // covers int8-quant + bf16 sim-error differences
#define CAND   16                 // candidate slots per row

// int8 quantization: q = round(x * 16); |x|max ~5.7 -> |q| <= ~92
#define QS     16.0f
#define INVQS2 0.0078125f         // 2 / (QS*QS)

// ---------------- Device scratch (no allocations allowed) ----------------
__device__ __align__(16) __nv_bfloat16 g_eb[NCODE * DIMK];  // bf16 embedding
__device__ __align__(16) int8_t g_ei[NCODE * DIMK];         // int8 embedding
__device__ float g_ce[NCODE];             // ||e_n||^2 (fp32, exact)
__device__ int   g_cnt[N_ROWS];           // candidate counts
__device__ int   g_cand[N_ROWS * CAND];   // candidate lists
__device__ float g_part[EPI_BLOCKS];      // loss partials

// ---------------- PTX helpers (portable to compute_103) ----------------
__device__ __forceinline__ uint32_t smem_u32(const void* p) {
    uint32_t a;
    asm("{ .reg .u64 t; cvta.to.shared.u64 t, %1; cvt.u32.u64 %0, t; }" : "=r"(a) : "l"(p));
    return a;
}
#define CP_ASYNC16(dst, src) \
    asm volatile("cp.async.cg.shared.global [%0], [%1], 16;" :: "r"(dst), "l"(src) : "memory")
#define CP_COMMIT() asm volatile("cp.async.commit_group;" ::: "memory")
#define CP_WAIT0()  asm volatile("cp.async.wait_group 0;" ::: "memory")
#define LDSM4(r0, r1, r2, r3, addr) \
    asm volatile("ldmatrix.sync.aligned.m8n8.x4.shared.b16 {%0,%1,%2,%3}, [%4];" \
        : "=r"(r0), "=r"(r1), "=r"(r2), "=r"(r3) : "r"(addr))
#define MMA16816(d, a, b0, b1) \
    asm volatile("mma.sync.aligned.m16n8k16.row.col.f32.bf16.bf16.f32 " \
        "{%0,%1,%2,%3},{%4,%5,%6,%7},{%8,%9},{%0,%1,%2,%3};" \
        : "+f"((d)[0]), "+f"((d)[1]), "+f"((d)[2]), "+f"((d)[3]) \
        : "r"((a)[0]), "r"((a)[1]), "r"((a)[2]), "r"((a)[3]), "r"(b0), "r"(b1))
#define BAR_HMMA() asm volatile("bar.sync 1, 256;" ::: "memory")

// signed dp4a via PTX (avoids intrinsic overload ambiguity)
__device__ __forceinline__ int dp4a_s(unsigned a, unsigned b, int c) {
    int d;
    asm("dp4a.s32.s32 %0, %1, %2, %3;" : "=r"(d) : "r"(a), "r"(b), "r"(c));
    return d;
}

// Monotone float<->uint map for atomicMax on floats
__device__ __forceinline__ unsigned fmono(float x) {
    unsigned u = __float_as_uint(x);
    return (u & 0x80000000u) ? ~u : (u | 0x80000000u);
}
__device__ __forceinline__ float funmono(unsigned u) {
    return (u & 0x80000000u) ? __uint_as_float(u ^ 0x80000000u) : __uint_as_float(~u);
}

__device__ __forceinline__ unsigned quant4(float4 v) {
    int a = __float2int_rn(fminf(fmaxf(v.x * QS, -127.f), 127.f));
    int b = __float2int_rn(fminf(fmaxf(v.y * QS, -127.f), 127.f));
    int c = __float2int_rn(fminf(fmaxf(v.z * QS, -127.f), 127.f));
    int d = __float2int_rn(fminf(fmaxf(v.w * QS, -127.f), 127.f));
    return (unsigned)(a & 255) | ((unsigned)(b & 255) << 8) |
           ((unsigned)(c & 255) << 16) | ((unsigned)(d & 255) << 24);
}

// ---------------- SMEM layout for k_mma ----------------
// bf16 rows padded to 528B (264 bf16): conflict-reduced ldmatrix (R3-proven)
#define RSB 528
#define SM_CE  0                  // 512 f32 = 2048B
#define SM_RB  2048               // 128 u32 = 512B
#define SM_ABF 2560               // 128 * 528 = 67584 (bf16 A)
#define SM_BBF 70144              // 64 * 528 = 33792  (bf16 B sub-chunk)
#define SM_A8  103936             // uint2[32][128] = 32768 (int8 A, K-outer)
#define SM_B8  136704             // uint2[32][256] = 65536 (int8 B codes 256..511)
#define SMEM_BYTES 202240

// ---------------- Kernel: prep (bf16 + int8 emb, norms, zero counters/hist) ----------------
__global__ void k_prep(const float* __restrict__ emb, float* __restrict__ out) {
    int n = blockIdx.x;               // 512 blocks, 64 threads
    int t = threadIdx.x;
    float4 v = *(const float4*)(emb + (size_t)n * DIMK + t * 4);
    // bf16
    __nv_bfloat162 p0 = __floats2bfloat162_rn(v.x, v.y);
    __nv_bfloat162 p1 = __floats2bfloat162_rn(v.z, v.w);
    uint2 wb;
    wb.x = *(unsigned*)&p0;
    wb.y = *(unsigned*)&p1;
    *(uint2*)((char*)g_eb + (size_t)n * 512 + t * 8) = wb;
    // int8
    ((unsigned*)g_ei)[n * 64 + t] = quant4(v);
    // exact fp32 norm
    float s = v.x * v.x + v.y * v.y + v.z * v.z + v.w * v.w;
    #pragma unroll
    for (int o = 16; o > 0; o >>= 1) s += __shfl_down_sync(0xffffffffu, s, o);
    __shared__ float ws[2];
    if ((t & 31) == 0) ws[t >> 5] = s;
    __syncthreads();
    if (t == 0) g_ce[n] = ws[0] + ws[1];
    // zero candidate counters
    int g = n * 64 + t;
    #pragma unroll
    for (int k = 0; k < 4; k++) g_cnt[g + k * 32768] = 0;
    // zero histogram
    if (n == 0) {
        #pragma unroll
        for (int k = 0; k < 8; k++) out[HIST_OFF + t + k * 64] = 0.0f;
    }
}

// ---------------- Kernel: hybrid HMMA(bf16, codes 0..255) + dp4a(int8, codes 256..511) ----------------
__global__ __launch_bounds__(512, 1)
void k_mma(const float* __restrict__ z) {
    extern __shared__ __align__(128) unsigned char smem[];
    float*    ceS     = (float*)(smem + SM_CE);
    unsigned* rowBest = (unsigned*)(smem + SM_RB);
    uint2*    A8      = (uint2*)(smem + SM_A8);
    uint2*    B8      = (uint2*)(smem + SM_B8);
    uint32_t sb = smem_u32(smem);

    int tid = threadIdx.x, lane = tid & 31, wid = tid >> 5;
    int rowBase = blockIdx.x * 128;

    ceS[tid] = g_ce[tid];                 // 512 threads == NCODE
    if (tid < 128) rowBest[tid] = 0u;

    // ---- bf16 B sub-chunk 0 (codes 0..63) via cp.async ----
    #pragma unroll
    for (int it = 0; it < 4; it++) {
        int t = tid + it * 512;
        int r = t >> 5, c = t & 31;       // 64 rows x 32 16B-units
        CP_ASYNC16(sb + SM_BBF + r * RSB + c * 16, (const char*)g_eb + r * 512 + c * 16);
    }
    CP_COMMIT();

    // ---- A fill: fp32 z -> bf16 Abf AND int8 A8 (K-outer) ----
    {
        int row = tid >> 2, q = tid & 3;
        const float* zr = z + (size_t)(rowBase + row) * DIMK + q * 64;
        #pragma unroll
        for (int j = 0; j < 8; j++) {
            float4 v0 = *(const float4*)(zr + j * 8);
            float4 v1 = *(const float4*)(zr + j * 8 + 4);
            __nv_bfloat162 p0 = __floats2bfloat162_rn(v0.x, v0.y);
            __nv_bfloat162 p1 = __floats2bfloat162_rn(v0.z, v0.w);
            __nv_bfloat162 p2 = __floats2bfloat162_rn(v1.x, v1.y);
            __nv_bfloat162 p3 = __floats2bfloat162_rn(v1.z, v1.w);
            uint4 w;
            w.x = *(unsigned*)&p0; w.y = *(unsigned*)&p1;
            w.z = *(unsigned*)&p2; w.w = *(unsigned*)&p3;
            *(uint4*)(smem + SM_ABF + row * RSB + (q * 8 + j) * 16) = w;
            A8[(q * 8 + j) * 128 + row] = make_uint2(quant4(v0), quant4(v1));
        }
    }
    // ---- int8 B8 fill (codes 256..511, transposed to [kw2][code]) ----
    {
        int code = tid >> 1, h = tid & 1;  // local code 0..255
        const uint2* src = (const uint2*)((const char*)g_ei + (size_t)(256 + code) * 256);
        #pragma unroll
        for (int j = 0; j < 16; j++) {
            int kw2 = h * 16 + j;
            B8[kw2 * 256 + code] = src[kw2];
        }
    }
    CP_WAIT0();
    __syncthreads();

    if (wid < 8) {
        // ================= HMMA path: codes 0..255, 4 sub-chunks of 64 =================
        int wm = wid & 3, wn = wid >> 2;   // 32M x 32N warp tile
        uint32_t aA = sb + SM_ABF + (wm * 32 + (lane & 15)) * RSB + ((lane >> 4) << 4);
        uint32_t bOfs = (uint32_t)((wn * 32 + (lane & 7) + ((lane >> 4) << 3)) * RSB
                                   + (((lane >> 3) & 1) << 4));
        for (int sub = 0; sub < 4; sub++) {
            float acc[2][4][4];
            #pragma unroll
            for (int i = 0; i < 2; i++)
                #pragma unroll
                for (int j = 0; j < 4; j++)
                    #pragma unroll
                    for (int q = 0; q < 4; q++) acc[i][j][q] = 0.0f;

            uint32_t bB = sb + SM_BBF + bOfs;
            #pragma unroll
            for (int ks = 0; ks < 16; ks++) {
                uint32_t ko = ks * 32;
                uint32_t a0[4], a1[4];
                LDSM4(a0[0], a0[1], a0[2], a0[3], aA + ko);
                LDSM4(a1[0], a1[1], a1[2], a1[3], aA + 16 * RSB + ko);
                #pragma unroll
                for (int p = 0; p < 2; p++) {
                    uint32_t b0, b1, b2, b3;
                    LDSM4(b0, b1, b2, b3, bB + p * (16 * RSB) + ko);
                    MMA16816(acc[0][2 * p],     a0, b0, b1);
                    MMA16816(acc[0][2 * p + 1], a0, b2, b3);
                    MMA16816(acc[1][2 * p],     a1, b0, b1);
                    MMA16816(acc[1][2 * p + 1], a1, b2, b3);
                }
            }
            BAR_HMMA();   // all HMMA warps done reading Bbf

            if (sub < 3) {   // issue next sub-chunk load (256 threads, 8 units each)
                const char* src = (const char*)g_eb + (size_t)(sub + 1) * 64 * 512;
                #pragma unroll
                for (int it = 0; it < 8; it++) {
                    int t = tid + it * 256;
                    int r = t >> 5, c = t & 31;
                    CP_ASYNC16(sb + SM_BBF + r * RSB + c * 16, src + r * 512 + c * 16);
                }
                CP_COMMIT();
            }

            int cbase = sub * 64 + wn * 32 + 2 * (lane & 3);
            // pass 1: per-row max
            #pragma unroll
            for (int mh = 0; mh < 2; mh++) {
                #pragma unroll
                for (int rr = 0; rr < 2; rr++) {
                    float m = -3.0e38f;
                    #pragma unroll
                    for (int nb = 0; nb < 4; nb++) {
                        float v0 = fmaf(-2.0f, acc[mh][nb][rr * 2],     ceS[cbase + nb * 8]);
                        float v1 = fmaf(-2.0f, acc[mh][nb][rr * 2 + 1], ceS[cbase + nb * 8 + 1]);
                        m = fmaxf(m, fmaxf(v0, v1));
                    }
                    m = fmaxf(m, __shfl_xor_sync(0xffffffffu, m, 1));
                    m = fmaxf(m, __shfl_xor_sync(0xffffffffu, m, 2));
                    if ((lane & 3) == 0)
                        atomicMax(&rowBest[wm * 32 + mh * 16 + rr * 8 + (lane >> 2)], fmono(m));
                }
            }
            BAR_HMMA();   // rowBest coherent across HMMA warps
            // pass 2: collect candidates (superset-safe)
            #pragma unroll
            for (int mh = 0; mh < 2; mh++) {
                #pragma unroll
                for (int rr = 0; rr < 2; rr++) {
                    int lrow = wm * 32 + mh * 16 + rr * 8 + (lane >> 2);
                    float thr = funmono(rowBest[lrow]) - MARGIN;
                    int grow = rowBase + lrow;
                    #pragma unroll
                    for (int nb = 0; nb < 4; nb++) {
                        #pragma unroll
                        for (int q = 0; q < 2; q++) {
                            int col = cbase + nb * 8 + q;
                            float v = fmaf(-2.0f, acc[mh][nb][rr * 2 + q], ceS[col]);
                            if (v >= thr) {
                                int pos = atomicAdd(&g_cnt[grow], 1);
                                if (pos < CAND) g_cand[grow * CAND + pos] = col;
                            }
                        }
                    }
                }
            }
            if (sub < 3) { CP_WAIT0(); BAR_HMMA(); }
        }
    } else {
        // ================= dp4a path: codes 256..511, 2 passes of 128 =================
        int wq = wid - 8;
        int wm2 = wq & 3, wc = wq >> 2;    // 32 rows, 64-code half
        int rg = lane >> 3, cg = lane & 7; // thread: 8 rows x 8 codes
        #pragma unroll 1
        for (int p = 0; p < 2; p++) {
            int acc[8][8];
            #pragma unroll
            for (int i = 0; i < 8; i++)
                #pragma unroll
                for (int j = 0; j < 8; j++) acc[i][j] = 0;

            int cbaseL = p * 128 + wc * 64 + cg;   // local code (global = 256 + local)
            int rbase = wm2 * 32 + rg;
            #pragma unroll 1
            for (int kw2 = 0; kw2 < 32; kw2++) {
                uint2 Ar[8], Br[8];
                const uint2* Ak = A8 + kw2 * 128 + rbase;
                const uint2* Bk = B8 + kw2 * 256 + cbaseL;
                #pragma unroll
                for (int i = 0; i < 8; i++) Ar[i] = Ak[4 * i];
                #pragma unroll
                for (int j = 0; j < 8; j++) Br[j] = Bk[8 * j];
                #pragma unroll
                for (int i = 0; i < 8; i++)
                    #pragma unroll
                    for (int j = 0; j < 8; j++) {
                        acc[i][j] = dp4a_s(Ar[i].x, Br[j].x, acc[i][j]);
                        acc[i][j] = dp4a_s(Ar[i].y, Br[j].y, acc[i][j]);
                    }
            }

            // epilogue: per-row max + candidates (thread-private rows -> no sync)
            #pragma unroll
            for (int i = 0; i < 8; i++) {
                int lrow = rbase + 4 * i;
                int grow = rowBase + lrow;
                float v[8], m = -3.0e38f;
                #pragma unroll
                for (int j = 0; j < 8; j++) {
                    v[j] = fmaf((float)acc[i][j], -INVQS2, ceS[256 + cbaseL + 8 * j]);
                    m = fmaxf(m, v[j]);
                }
                unsigned mm = fmono(m);
                unsigned old = atomicMax(&rowBest[lrow], mm);
                float thr = funmono(old > mm ? old : mm) - MARGIN;
                #pragma unroll
                for (int j = 0; j < 8; j++) {
                    if (v[j] >= thr) {
                        int pos = atomicAdd(&g_cnt[grow], 1);
                        if (pos < CAND) g_cand[grow * CAND + pos] = 256 + cbaseL + 8 * j;
                    }
                }
            }
        }
    }
}

// ---------------- Kernel: fused resolve + gather epilogue ----------------
__global__ __launch_bounds__(256)
void k_epi(const float* __restrict__ z, const float* __restrict__ emb,
           float* __restrict__ out) {
    int w = threadIdx.x >> 5;
    int l = threadIdx.x & 31;
    int row = blockIdx.x * 8 + w;

    const float4* zp = (const float4*)(z + (size_t)row * DIMK);
    float4 a = zp[l * 2], b = zp[l * 2 + 1];

    // ---- resolve index ----
    int cnt = g_cnt[row];
    int idx;
    if (cnt <= 1) {
        idx = (cnt == 1) ? g_cand[row * CAND] : 0;
    } else {
        float best = -3.0e38f;
        idx = NCODE;
        bool full = (cnt > CAND);
        int n = full ? NCODE : cnt;
        for (int ci = 0; ci < n; ci++) {
            int c = full ? ci : g_cand[row * CAND + ci];
            const float4* ep = (const float4*)(emb + (size_t)c * DIMK);
            float4 e0 = ep[l * 2], e1 = ep[l * 2 + 1];
            float s = a.x * e0.x + a.y * e0.y + a.z * e0.z + a.w * e0.w
                    + b.x * e1.x + b.y * e1.y + b.z * e1.z + b.w * e1.w;
            #pragma unroll
            for (int o = 16; o > 0; o >>= 1) s += __shfl_xor_sync(0xffffffffu, s, o);
            float sim = g_ce[c] - 2.0f * s;
            if (sim > best || (sim == best && c < idx)) { best = sim; idx = c; }
        }
    }

    // ---- gather + loss ----
    const float* er = emb + (size_t)idx * DIMK;
    float* oq = out + ZQ_OFF + (size_t)row * DIMK;
    float4 e0 = *(const float4*)(er + l * 8);
    float4 e1 = *(const float4*)(er + l * 8 + 4);
    *(float4*)(oq + l * 8)     = e0;
    *(float4*)(oq + l * 8 + 4) = e1;
    float d0 = e0.x - a.x, d1 = e0.y - a.y, d2 = e0.z - a.z, d3 = e0.w - a.w;
    float d4 = e1.x - b.x, d5 = e1.y - b.y, d6 = e1.z - b.z, d7 = e1.w - b.w;
    float s = d0 * d0 + d1 * d1 + d2 * d2 + d3 * d3
            + d4 * d4 + d5 * d5 + d6 * d6 + d7 * d7;
    #pragma unroll
    for (int o = 16; o > 0; o >>= 1) s += __shfl_down_sync(0xffffffffu, s, o);

    __shared__ float ws[8];
    if (l == 0) {
        ws[w] = s;
        out[IDX_OFF + row] = (float)idx;
        atomicAdd(&out[HIST_OFF + idx], 1.0f);  // exact: integer-valued float adds
    }
    __syncthreads();
    if (threadIdx.x == 0) {
        float t = 0.0f;
        #pragma unroll
        for (int i = 0; i < 8; i++) t += ws[i];
        g_part[blockIdx.x] = t;
    }
}

// ---------------- Kernel: finalize losses ----------------
__global__ void k_final(float* __restrict__ out) {
    __shared__ float ps[256];
    int t = threadIdx.x;
    float s = 0.0f;
    for (int i = t; i < EPI_BLOCKS; i += 256) s += g_part[i];
    ps[t] = s;
    __syncthreads();
    if (t == 0) {
        float tot = 0.0f;
        for (int i = 0; i < 256; i++) tot += ps[i];
        float vq = tot / 33554432.0f;   // N_ROWS * DIMK
        out[VQ_OFF] = vq;
        out[CM_OFF] = 0.25f * vq;
    }
}

// ---------------- Launch ----------------
extern "C" void kernel_launch(void* const* d_in, const int* in_sizes, int n_in,
                              void* d_out, int out_size) {
    const float* z   = (const float*)d_in[0];
    const float* emb = (const float*)d_in[1];
    float* out = (float*)d_out;

    cudaFuncSetAttribute(k_mma, cudaFuncAttributeMaxDynamicSharedMemorySize, SMEM_BYTES);

    k_prep<<<NCODE, 64>>>(emb, out);
    k_mma<<<N_ROWS / 128, 512, SMEM_BYTES>>>(z);
    k_epi<<<EPI_BLOCKS, 256>>>(z, emb, out);
    k_final<<<1, 256>>>(out);
}

// round 8
// speedup vs baseline: 1.7446x; 1.7313x over previous
#include <cuda_runtime.h>
#include <cuda_bf16.h>
#include <cstdint>

// ---------------- Problem constants ----------------
#define N_ROWS   131072      // 32*16*16*16
#define DIMK     256         // E_DIM
#define NCODE    512         // N_EMBED

// Output layout (concatenated flattened outputs, float32):
#define ZQ_OFF   0
#define VQ_OFF   33554432
#define CM_OFF   33554433
#define IDX_OFF  33554434
#define HIST_OFF 33685506

#define NBLK (N_ROWS / 128)       // 1024 main blocks
#define MARGIN 0.8f               // ~6 sigma of bf16 sim-error difference (R3-proven)
#define CAND   12                 // candidate slots per row

// ---------------- Device scratch (no allocations allowed) ----------------
__device__ __align__(16) __nv_bfloat16 g_eb[NCODE * DIMK];  // bf16 embedding
__device__ float g_ce[NCODE];             // ||e_n||^2 (fp32, exact)
__device__ float g_part[NBLK];            // loss partials

// ---------------- PTX helpers (portable to compute_103) ----------------
__device__ __forceinline__ uint32_t smem_u32(const void* p) {
    uint32_t a;
    asm("{ .reg .u64 t; cvta.to.shared.u64 t, %1; cvt.u32.u64 %0, t; }" : "=r"(a) : "l"(p));
    return a;
}
#define CP_ASYNC16(dst, src) \
    asm volatile("cp.async.cg.shared.global [%0], [%1], 16;" :: "r"(dst), "l"(src) : "memory")
#define CP_COMMIT() asm volatile("cp.async.commit_group;" ::: "memory")
#define CP_WAIT0()  asm volatile("cp.async.wait_group 0;" ::: "memory")
#define LDSM4(r0, r1, r2, r3, addr) \
    asm volatile("ldmatrix.sync.aligned.m8n8.x4.shared.b16 {%0,%1,%2,%3}, [%4];" \
        : "=r"(r0), "=r"(r1), "=r"(r2), "=r"(r3) : "r"(addr))
#define MMA16816(d, a, b0, b1) \
    asm volatile("mma.sync.aligned.m16n8k16.row.col.f32.bf16.bf16.f32 " \
        "{%0,%1,%2,%3},{%4,%5,%6,%7},{%8,%9},{%0,%1,%2,%3};" \
        : "+f"((d)[0]), "+f"((d)[1]), "+f"((d)[2]), "+f"((d)[3]) \
        : "r"((a)[0]), "r"((a)[1]), "r"((a)[2]), "r"((a)[3]), "r"(b0), "r"(b1))

// Monotone float<->uint map for atomicMax on floats
__device__ __forceinline__ unsigned fmono(float x) {
    unsigned u = __float_as_uint(x);
    return (u & 0x80000000u) ? ~u : (u | 0x80000000u);
}
__device__ __forceinline__ float funmono(unsigned u) {
    return (u & 0x80000000u) ? __uint_as_float(u ^ 0x80000000u) : __uint_as_float(~u);
}

// ---------------- SMEM layout for k_mma ----------------
// bf16 rows padded to 528B (264 bf16): conflict-reduced ldmatrix (R3-proven)
#define RS 528
#define SM_CE   0                 // 512 f32 = 2048B
#define SM_RB   2048              // 128 u32 = 512B
#define SM_CNT  2560              // 128 s32 = 512B
#define SM_CAND 3072              // 128 * CAND s32 = 6144B
#define SM_A    9216              // 128 * 528 = 67584
#define SM_B0   76800             // 128 * 528
#define SM_B1   144384            // 128 * 528
#define SMEM_BYTES 211968

// ---------------- Kernel: prep (convert emb, norms, zero hist) ----------------
__global__ void k_prep(const float* __restrict__ emb, float* __restrict__ out) {
    int n = blockIdx.x;               // 512 blocks, 64 threads
    int t = threadIdx.x;
    float4 v = *(const float4*)(emb + (size_t)n * DIMK + t * 4);
    __nv_bfloat162 p0 = __floats2bfloat162_rn(v.x, v.y);
    __nv_bfloat162 p1 = __floats2bfloat162_rn(v.z, v.w);
    uint2 w;
    w.x = *(unsigned*)&p0;
    w.y = *(unsigned*)&p1;
    *(uint2*)((char*)g_eb + (size_t)n * 512 + t * 8) = w;
    float s = v.x * v.x + v.y * v.y + v.z * v.z + v.w * v.w;
    #pragma unroll
    for (int o = 16; o > 0; o >>= 1) s += __shfl_down_sync(0xffffffffu, s, o);
    __shared__ float ws[2];
    if ((t & 31) == 0) ws[t >> 5] = s;
    __syncthreads();
    if (t == 0) g_ce[n] = ws[0] + ws[1];
    if (n == 0) {
        #pragma unroll
        for (int k = 0; k < 8; k++) out[HIST_OFF + t + k * 64] = 0.0f;
    }
}

// ---------------- Kernel: HMMA GEMM + candidates + fused resolve/gather/loss ----------------
__global__ __launch_bounds__(256, 1)
void k_mma(const float* __restrict__ z, const float* __restrict__ emb,
           float* __restrict__ out) {
    extern __shared__ __align__(128) unsigned char smem[];
    float*    ceS     = (float*)(smem + SM_CE);
    unsigned* rowBest = (unsigned*)(smem + SM_RB);
    int*      sCnt    = (int*)(smem + SM_CNT);
    int*      sCand   = (int*)(smem + SM_CAND);
    uint32_t sbase = smem_u32(smem);
    uint32_t sA  = sbase + SM_A;
    uint32_t sB[2] = { sbase + SM_B0, sbase + SM_B1 };

    int tid = threadIdx.x, lane = tid & 31, wid = tid >> 5;
    int wm = wid & 3;        // M block: 32 rows
    int wn = wid >> 2;       // N block: 64 cols
    int rowBase = blockIdx.x * 128;

    for (int i = tid; i < NCODE; i += 256) ceS[i] = g_ce[i];
    if (tid < 128) { rowBest[tid] = 0u; sCnt[tid] = 0; }

    // ---- prefetch B chunk 0 ----
    {
        const char* src = (const char*)g_eb;
        #pragma unroll
        for (int it = 0; it < 16; it++) {
            int t = tid + it * 256;
            int r = t >> 5, c = t & 31;
            CP_ASYNC16(sB[0] + r * RS + c * 16, src + r * 512 + c * 16);
        }
        CP_COMMIT();
    }

    // ---- load + convert A tile: 128 rows x 256 fp32 -> bf16, padded rows ----
    #pragma unroll
    for (int it = 0; it < 16; it++) {
        int t = tid + it * 256;
        int r = t >> 5, c = t & 31;
        const float4* zp = (const float4*)(z + (size_t)(rowBase + r) * DIMK + c * 8);
        float4 u0 = zp[0], u1 = zp[1];
        __nv_bfloat162 p0 = __floats2bfloat162_rn(u0.x, u0.y);
        __nv_bfloat162 p1 = __floats2bfloat162_rn(u0.z, u0.w);
        __nv_bfloat162 p2 = __floats2bfloat162_rn(u1.x, u1.y);
        __nv_bfloat162 p3 = __floats2bfloat162_rn(u1.z, u1.w);
        uint4 w;
        w.x = *(unsigned*)&p0; w.y = *(unsigned*)&p1;
        w.z = *(unsigned*)&p2; w.w = *(unsigned*)&p3;
        *(uint4*)(smem + SM_A + r * RS + c * 16) = w;
    }
    CP_WAIT0();
    __syncthreads();

    // ldmatrix base addresses
    uint32_t aA0 = sA + (wm * 32 + (lane & 15)) * RS + ((lane >> 4) << 4);
    uint32_t aA1 = aA0 + 16 * RS;
    uint32_t bBofs = (uint32_t)((wn * 64 + (lane & 7) + ((lane >> 4) << 3)) * RS
                                + (((lane >> 3) & 1) << 4));

    for (int ch = 0; ch < 4; ch++) {
        // prefetch next B chunk
        if (ch < 3) {
            const char* src = (const char*)g_eb + (size_t)(ch + 1) * 128 * 512;
            uint32_t dB = sB[(ch + 1) & 1];
            #pragma unroll
            for (int it = 0; it < 16; it++) {
                int t = tid + it * 256;
                int r = t >> 5, c = t & 31;
                CP_ASYNC16(dB + r * RS + c * 16, src + r * 512 + c * 16);
            }
            CP_COMMIT();
        }

        // ---- compute chunk ch ----
        float acc[2][8][4];
        #pragma unroll
        for (int i = 0; i < 2; i++)
            #pragma unroll
            for (int j = 0; j < 8; j++)
                #pragma unroll
                for (int q = 0; q < 4; q++) acc[i][j][q] = 0.0f;

        uint32_t bB = sB[ch & 1] + bBofs;
        #pragma unroll
        for (int ks = 0; ks < 16; ks++) {
            uint32_t ko = ks * 32;
            uint32_t a[2][4];
            LDSM4(a[0][0], a[0][1], a[0][2], a[0][3], aA0 + ko);
            LDSM4(a[1][0], a[1][1], a[1][2], a[1][3], aA1 + ko);
            #pragma unroll
            for (int p = 0; p < 4; p++) {
                uint32_t b0, b1, b2, b3;
                LDSM4(b0, b1, b2, b3, bB + p * (16 * RS) + ko);
                MMA16816(acc[0][2 * p],     a[0], b0, b1);
                MMA16816(acc[0][2 * p + 1], a[0], b2, b3);
                MMA16816(acc[1][2 * p],     a[1], b0, b1);
                MMA16816(acc[1][2 * p + 1], a[1], b2, b3);
            }
        }

        int cbase = ch * 128 + wn * 64 + (lane & 3) * 2;

        // ---- pass 1: per-row running max into smem (monotone atomicMax) ----
        #pragma unroll
        for (int im = 0; im < 2; im++) {
            #pragma unroll
            for (int h = 0; h < 2; h++) {
                float m = -3.0e38f;
                #pragma unroll
                for (int jn = 0; jn < 8; jn++) {
                    float v0 = fmaf(-2.0f, acc[im][jn][h * 2],     ceS[cbase + jn * 8]);
                    float v1 = fmaf(-2.0f, acc[im][jn][h * 2 + 1], ceS[cbase + jn * 8 + 1]);
                    m = fmaxf(m, fmaxf(v0, v1));
                }
                m = fmaxf(m, __shfl_xor_sync(0xffffffffu, m, 1));
                m = fmaxf(m, __shfl_xor_sync(0xffffffffu, m, 2));
                if ((lane & 3) == 0)
                    atomicMax(&rowBest[wm * 32 + im * 16 + h * 8 + (lane >> 2)], fmono(m));
            }
        }
        __syncthreads();

        // ---- pass 2: collect candidates v >= rowBest - MARGIN (superset-safe) ----
        #pragma unroll
        for (int im = 0; im < 2; im++) {
            #pragma unroll
            for (int h = 0; h < 2; h++) {
                int lrow = wm * 32 + im * 16 + h * 8 + (lane >> 2);
                float thr = funmono(rowBest[lrow]) - MARGIN;
                #pragma unroll
                for (int jn = 0; jn < 8; jn++) {
                    #pragma unroll
                    for (int q = 0; q < 2; q++) {
                        int col = cbase + jn * 8 + q;
                        float v = fmaf(-2.0f, acc[im][jn][h * 2 + q], ceS[col]);
                        if (v >= thr) {
                            int pos = atomicAdd(&sCnt[lrow], 1);
                            if (pos < CAND) sCand[lrow * CAND + pos] = col;
                        }
                    }
                }
            }
        }
        // rowBest only grows -> later (tighter) thresholds remain superset-safe

        if (ch < 3) {
            CP_WAIT0();
            __syncthreads();
        }
    }
    __syncthreads();

    // =============== fused epilogue: resolve + gather + loss + hist ===============
    float lossAcc = 0.0f;
    #pragma unroll 1
    for (int rr = 0; rr < 16; rr++) {
        int lrow = wid * 16 + rr;
        int row = rowBase + lrow;

        const float4* zp = (const float4*)(z + (size_t)row * DIMK);
        float4 a = zp[lane * 2], b = zp[lane * 2 + 1];

        int cnt = sCnt[lrow];
        int idx;
        if (cnt == 1) {
            idx = sCand[lrow * CAND];
        } else {
            float best = -3.0e38f;
            idx = NCODE;
            bool full = (cnt > CAND);
            int n = full ? NCODE : cnt;
            #pragma unroll 1
            for (int ci = 0; ci < n; ci++) {
                int c = full ? ci : sCand[lrow * CAND + ci];
                const float4* ep = (const float4*)(emb + (size_t)c * DIMK);
                float4 e0 = ep[lane * 2], e1 = ep[lane * 2 + 1];
                float s = a.x * e0.x + a.y * e0.y + a.z * e0.z + a.w * e0.w
                        + b.x * e1.x + b.y * e1.y + b.z * e1.z + b.w * e1.w;
                #pragma unroll
                for (int o = 16; o > 0; o >>= 1) s += __shfl_xor_sync(0xffffffffu, s, o);
                float sim = ceS[c] - 2.0f * s;
                if (sim > best || (sim == best && c < idx)) { best = sim; idx = c; }
            }
        }

        const float* er = emb + (size_t)idx * DIMK;
        float* oq = out + ZQ_OFF + (size_t)row * DIMK;
        float4 e0 = *(const float4*)(er + lane * 8);
        float4 e1 = *(const float4*)(er + lane * 8 + 4);
        *(float4*)(oq + lane * 8)     = e0;
        *(float4*)(oq + lane * 8 + 4) = e1;
        float d0 = e0.x - a.x, d1 = e0.y - a.y, d2 = e0.z - a.z, d3 = e0.w - a.w;
        float d4 = e1.x - b.x, d5 = e1.y - b.y, d6 = e1.z - b.z, d7 = e1.w - b.w;
        lossAcc += d0 * d0 + d1 * d1 + d2 * d2 + d3 * d3
                 + d4 * d4 + d5 * d5 + d6 * d6 + d7 * d7;

        if (lane == 0) {
            out[IDX_OFF + row] = (float)idx;
            atomicAdd(&out[HIST_OFF + idx], 1.0f);  // exact: integer-valued float adds
        }
    }

    // block-reduce loss partial (fixed order -> deterministic)
    #pragma unroll
    for (int o = 16; o > 0; o >>= 1) lossAcc += __shfl_down_sync(0xffffffffu, lossAcc, o);
    __shared__ float ws[8];
    if (lane == 0) ws[wid] = lossAcc;
    __syncthreads();
    if (tid == 0) {
        float t = 0.0f;
        #pragma unroll
        for (int i = 0; i < 8; i++) t += ws[i];
        g_part[blockIdx.x] = t;
    }
}

// ---------------- Kernel: finalize losses ----------------
__global__ void k_final(float* __restrict__ out) {
    __shared__ float ps[256];
    int t = threadIdx.x;
    float s = 0.0f;
    for (int i = t; i < NBLK; i += 256) s += g_part[i];   // fixed order
    ps[t] = s;
    __syncthreads();
    if (t == 0) {
        float tot = 0.0f;
        for (int i = 0; i < 256; i++) tot += ps[i];       // fixed order
        float vq = tot / 33554432.0f;   // N_ROWS * DIMK
        out[VQ_OFF] = vq;
        out[CM_OFF] = 0.25f * vq;
    }
}

// ---------------- Launch ----------------
extern "C" void kernel_launch(void* const* d_in, const int* in_sizes, int n_in,
                              void* d_out, int out_size) {
    const float* z   = (const float*)d_in[0];
    const float* emb = (const float*)d_in[1];
    float* out = (float*)d_out;

    cudaFuncSetAttribute(k_mma, cudaFuncAttributeMaxDynamicSharedMemorySize, SMEM_BYTES);

    k_prep<<<NCODE, 64>>>(emb, out);
    k_mma<<<NBLK, 256, SMEM_BYTES>>>(z, emb, out);
    k_final<<<1, 256>>>(out);
}